// round 2
// baseline (speedup 1.0000x reference)
#include <cuda_runtime.h>
#include <math.h>

#define MAXN 50000
#define MAXE 800000
#define MAXR 2000
#define FF   128
#define FD   384
#define PP   64
#define EPSV 1e-12f

// ------------------------ scratch (device globals, no allocs) ------------------
__device__ int   g_deg[MAXN];
__device__ int   g_rowptr[MAXN + 1];
__device__ int   g_cursor[MAXN];
__device__ int   g_perm[MAXE];
__device__ float g_relnorm[MAXR * FF];
__device__ float g_ttab[4 * MAXR];          // (dual*2+layer)*R + r
__device__ float g_smax[4 * MAXN];
__device__ float g_ssum[4 * MAXN];
__device__ float g_out[2][(size_t)MAXN * FD];   // concat features per dual
__device__ float g_pf[2][(size_t)MAXN * FD];    // proxy_feature per dual
__device__ float g_pinv[2][PP];                 // proxy row inverse norms

__device__ __forceinline__ float wsum(float v) {
#pragma unroll
    for (int o = 16; o; o >>= 1) v += __shfl_xor_sync(0xffffffffu, v, o);
    return v;
}
__device__ __forceinline__ float wmax(float v) {
#pragma unroll
    for (int o = 16; o; o >>= 1) v = fmaxf(v, __shfl_xor_sync(0xffffffffu, v, o));
    return v;
}

// ------------------------ CSR build ------------------------
__global__ void zero_deg_kernel(int N_) {
    int i = blockIdx.x * blockDim.x + threadIdx.x;
    if (i < N_) g_deg[i] = 0;
}

__global__ void count_kernel(const int* __restrict__ edst, int E_) {
    int e = blockIdx.x * blockDim.x + threadIdx.x;
    if (e < E_) atomicAdd(&g_deg[edst[e]], 1);
}

__global__ void scan_kernel(int N_) {
    __shared__ int sh[1024];
    __shared__ int carry;
    if (threadIdx.x == 0) carry = 0;
    __syncthreads();
    for (int base = 0; base < N_; base += 1024) {
        int i = base + threadIdx.x;
        int v = (i < N_) ? g_deg[i] : 0;
        sh[threadIdx.x] = v;
        __syncthreads();
#pragma unroll
        for (int off = 1; off < 1024; off <<= 1) {
            int t = (threadIdx.x >= off) ? sh[threadIdx.x - off] : 0;
            __syncthreads();
            sh[threadIdx.x] += t;
            __syncthreads();
        }
        int inc = sh[threadIdx.x];
        int exc = inc - v + carry;
        if (i < N_) { g_rowptr[i] = exc; g_cursor[i] = exc; }
        __syncthreads();
        if (threadIdx.x == 1023) carry += sh[1023];
        __syncthreads();
    }
    if (threadIdx.x == 0) g_rowptr[N_] = carry;
}

__global__ void scatter_kernel(const int* __restrict__ edst, int E_) {
    int e = blockIdx.x * blockDim.x + threadIdx.x;
    if (e < E_) {
        int p = atomicAdd(&g_cursor[edst[e]], 1);
        g_perm[p] = e;
    }
}

// ------------------------ relation normalization + attn tables ------------------
__global__ void relnorm_kernel(const float* __restrict__ rel,
                               const float* __restrict__ attn_e,
                               const float* __restrict__ attn_r, int R_) {
    int w = (blockIdx.x * blockDim.x + threadIdx.x) >> 5;
    int lane = threadIdx.x & 31;
    if (w >= R_) return;
    float4 v = *(const float4*)(rel + (size_t)w * FF + lane * 4);
    float ss = v.x * v.x + v.y * v.y + v.z * v.z + v.w * v.w;
    ss = wsum(ss);
    float inv = 1.f / fmaxf(sqrtf(ss), EPSV);
    float4 rn = make_float4(v.x * inv, v.y * inv, v.z * inv, v.w * inv);
    *(float4*)(g_relnorm + (size_t)w * FF + lane * 4) = rn;

    float4 a0 = *(const float4*)(attn_e + lane * 4);
    float4 a1 = *(const float4*)(attn_e + FF + lane * 4);
    float4 a2 = *(const float4*)(attn_r + lane * 4);
    float4 a3 = *(const float4*)(attn_r + FF + lane * 4);
    float d0 = wsum(rn.x * a0.x + rn.y * a0.y + rn.z * a0.z + rn.w * a0.w);
    float d1 = wsum(rn.x * a1.x + rn.y * a1.y + rn.z * a1.z + rn.w * a1.w);
    float d2 = wsum(rn.x * a2.x + rn.y * a2.y + rn.z * a2.z + rn.w * a2.w);
    float d3 = wsum(rn.x * a3.x + rn.y * a3.y + rn.z * a3.z + rn.w * a3.w);
    if (lane == 0) {
        g_ttab[0 * R_ + w] = d0;
        g_ttab[1 * R_ + w] = d1;
        g_ttab[2 * R_ + w] = d2;
        g_ttab[3 * R_ + w] = d3;
    }
}

// ------------------------ edge-softmax stats (all 4 tables at once) -------------
__global__ void __launch_bounds__(256) stats_kernel(const int* __restrict__ erel, int N_, int R_) {
    __shared__ float tab[4 * MAXR];
    int tid = threadIdx.x;
    for (int i = tid; i < 4 * R_; i += blockDim.x) tab[i] = g_ttab[i];
    __syncthreads();
    int warp = tid >> 5, lane = tid & 31;
    for (int n = blockIdx.x * 8 + warp; n < N_; n += gridDim.x * 8) {
        int s = g_rowptr[n], e = g_rowptr[n + 1];
        float m0 = -1e30f, m1 = -1e30f, m2 = -1e30f, m3 = -1e30f;
        for (int i = s + lane; i < e; i += 32) {
            int r = erel[g_perm[i]];
            m0 = fmaxf(m0, tab[r]);
            m1 = fmaxf(m1, tab[R_ + r]);
            m2 = fmaxf(m2, tab[2 * R_ + r]);
            m3 = fmaxf(m3, tab[3 * R_ + r]);
        }
        m0 = wmax(m0); m1 = wmax(m1); m2 = wmax(m2); m3 = wmax(m3);
        float s0 = 0, s1 = 0, s2 = 0, s3 = 0;
        for (int i = s + lane; i < e; i += 32) {
            int r = erel[g_perm[i]];
            s0 += __expf(tab[r] - m0);
            s1 += __expf(tab[R_ + r] - m1);
            s2 += __expf(tab[2 * R_ + r] - m2);
            s3 += __expf(tab[3 * R_ + r] - m3);
        }
        s0 = wsum(s0); s1 = wsum(s1); s2 = wsum(s2); s3 = wsum(s3);
        if (lane == 0) {
            g_smax[0 * N_ + n] = m0; g_ssum[0 * N_ + n] = s0;
            g_smax[1 * N_ + n] = m1; g_ssum[1 * N_ + n] = s1;
            g_smax[2 * N_ + n] = m2; g_ssum[2 * N_ + n] = s2;
            g_smax[3 * N_ + n] = m3; g_ssum[3 * N_ + n] = s3;
        }
    }
}

// ------------------------ initial mean features (both duals) --------------------
__global__ void __launch_bounds__(256) init_kernel(const float* __restrict__ ent,
                                                   const float* __restrict__ rel,
                                                   const int* __restrict__ esrc,
                                                   const int* __restrict__ erel, int N_) {
    int w = (blockIdx.x * blockDim.x + threadIdx.x) >> 5;
    if (w >= N_) return;
    int lane = threadIdx.x & 31;
    int s = g_rowptr[w], e = g_rowptr[w + 1];
    float4 ae = make_float4(0, 0, 0, 0), ar = make_float4(0, 0, 0, 0);
    for (int i = s; i < e; i++) {
        int ed = g_perm[i];
        int u = esrc[ed], r = erel[ed];
        float4 fe = *(const float4*)(ent + (size_t)u * FF + lane * 4);
        float4 fr = *(const float4*)(rel + (size_t)r * FF + lane * 4);
        ae.x += fe.x; ae.y += fe.y; ae.z += fe.z; ae.w += fe.w;
        ar.x += fr.x; ar.y += fr.y; ar.z += fr.z; ar.w += fr.w;
    }
    float inv = 1.f / fmaxf((float)(e - s), 1.f);
    float* oe = &g_out[0][(size_t)w * FD + lane * 4];
    float* orr = &g_out[1][(size_t)w * FD + lane * 4];
    oe[0] = tanhf(ae.x * inv); oe[1] = tanhf(ae.y * inv);
    oe[2] = tanhf(ae.z * inv); oe[3] = tanhf(ae.w * inv);
    orr[0] = tanhf(ar.x * inv); orr[1] = tanhf(ar.y * inv);
    orr[2] = tanhf(ar.z * inv); orr[3] = tanhf(ar.w * inv);
}

// ------------------------ GNN layer (per dual, per layer) -----------------------
__global__ void __launch_bounds__(256) layer_kernel(const int* __restrict__ esrc,
                                                    const int* __restrict__ erel,
                                                    int dual, int layer, int N_, int R_) {
    int w = (blockIdx.x * blockDim.x + threadIdx.x) >> 5;
    if (w >= N_) return;
    int lane = threadIdx.x & 31;
    int s = g_rowptr[w], e = g_rowptr[w + 1];
    int t = dual * 2 + layer;
    const float* feats = g_out[dual];
    const float* tt = g_ttab + (size_t)t * R_;
    float smax = g_smax[(size_t)t * N_ + w];
    float invs = (e > s) ? 1.f / g_ssum[(size_t)t * N_ + w] : 0.f;
    int coff = layer * FF + lane * 4;
    float4 acc = make_float4(0, 0, 0, 0);
    for (int i = s; i < e; i++) {
        int ed = g_perm[i];
        int u = esrc[ed], r = erel[ed];
        float4 f = *(const float4*)(feats + (size_t)u * FD + coff);
        float4 rn = *(const float4*)(g_relnorm + (size_t)r * FF + lane * 4);
        float p = f.x * rn.x + f.y * rn.y + f.z * rn.z + f.w * rn.w;
        float dot = wsum(p);
        float wgt = __expf(tt[r] - smax) * invs;
        float c = 2.f * dot * wgt;
        acc.x += wgt * f.x - c * rn.x;
        acc.y += wgt * f.y - c * rn.y;
        acc.z += wgt * f.z - c * rn.z;
        acc.w += wgt * f.w - c * rn.w;
    }
    float* o = &g_out[dual][(size_t)w * FD + (layer + 1) * FF + lane * 4];
    o[0] = tanhf(acc.x); o[1] = tanhf(acc.y);
    o[2] = tanhf(acc.z); o[3] = tanhf(acc.w);
}

// ------------------------ proxy row inverse norms -------------------------------
__global__ void pinv_kernel(const float* __restrict__ pe, const float* __restrict__ pr) {
    int w = (blockIdx.x * blockDim.x + threadIdx.x) >> 5;
    if (w >= 2 * PP) return;
    int lane = threadIdx.x & 31;
    const float* p = (w < PP) ? pe : pr;
    int row = w & (PP - 1);
    float ss = 0;
#pragma unroll
    for (int j = 0; j < 12; j++) {
        float v = p[(size_t)row * FD + lane + 32 * j];
        ss += v * v;
    }
    ss = wsum(ss);
    if (lane == 0) g_pinv[w >= PP ? 1 : 0][row] = 1.f / fmaxf(sqrtf(ss), EPSV);
}

// ------------------------ F1: proxy attention + proxy_feature -------------------
__global__ void __launch_bounds__(256) f1_kernel(const float* __restrict__ proxy,
                                                 int dual, int N_) {
    extern __shared__ float sh[];
    float* psh = sh;                       // 64*385
    float* rsh = psh + PP * 385;           // 8*384
    float* ash = rsh + 8 * FD;             // 8*64
    float* ivn = ash + 8 * PP;             // 64
    int tid = threadIdx.x;
    for (int i = tid; i < PP * FD; i += blockDim.x) {
        int p = i / FD, k = i % FD;
        psh[p * 385 + k] = proxy[i];
    }
    if (tid < PP) ivn[tid] = g_pinv[dual][tid];
    __syncthreads();
    int warp = tid >> 5, lane = tid & 31;
    float* myrow = rsh + warp * FD;
    float* mya = ash + warp * PP;
    const float* O = g_out[dual];
    float* PFo = g_pf[dual];
    for (int n = blockIdx.x * 8 + warp; n < N_; n += gridDim.x * 8) {
        const float* orow = O + (size_t)n * FD;
        float rv[12];
        float ss = 0;
#pragma unroll
        for (int j = 0; j < 12; j++) {
            float v = orow[lane + 32 * j];
            rv[j] = v;
            myrow[lane + 32 * j] = v;
            ss += v * v;
        }
        ss = wsum(ss);
        float inr = 1.f / fmaxf(sqrtf(ss), EPSV);
        __syncwarp();
        float s0 = 0, s1 = 0;
        const float* pr0 = psh + lane * 385;
        const float* pr1 = psh + (lane + 32) * 385;
#pragma unroll 4
        for (int k = 0; k < FD; k++) {
            float rk = myrow[k];
            s0 = fmaf(rk, pr0[k], s0);
            s1 = fmaf(rk, pr1[k], s1);
        }
        s0 *= inr * ivn[lane];
        s1 *= inr * ivn[lane + 32];
        float m = wmax(fmaxf(s0, s1));
        float e0 = __expf(s0 - m), e1 = __expf(s1 - m);
        float inv = 1.f / wsum(e0 + e1);
        mya[lane] = e0 * inv;
        mya[lane + 32] = e1 * inv;
        __syncwarp();
        float acc[12];
#pragma unroll
        for (int j = 0; j < 12; j++) acc[j] = rv[j];
        for (int p = 0; p < PP; p++) {
            float ap = mya[p];
            const float* pp = psh + p * 385 + lane;
#pragma unroll
            for (int j = 0; j < 12; j++) acc[j] = fmaf(-ap, pp[32 * j], acc[j]);
        }
#pragma unroll
        for (int j = 0; j < 12; j++) PFo[(size_t)n * FD + lane + 32 * j] = acc[j];
        __syncwarp();
    }
}

// ------------------------ F2: gate GEMM + final blend ---------------------------
#define BM 128
#define BN 128
#define BK 16
#define TM 8
#define TN 8
__global__ void __launch_bounds__(256) f2_kernel(const float* __restrict__ W,
                                                 const float* __restrict__ bias,
                                                 int dual, float* __restrict__ out, int N_) {
    __shared__ float As[BK][BM];
    __shared__ float Bs[BK][BN];
    int tid = threadIdx.x;
    int tx = tid & 15, ty = tid >> 4;
    int rowBase = blockIdx.y * BM;
    int colBase = blockIdx.x * BN;
    const float* A = g_pf[dual];
    float acc[TM][TN];
#pragma unroll
    for (int i = 0; i < TM; i++)
#pragma unroll
        for (int j = 0; j < TN; j++) acc[i][j] = 0.f;

    for (int k0 = 0; k0 < FD; k0 += BK) {
#pragma unroll
        for (int ld = 0; ld < 2; ld++) {
            int idx = tid + ld * 256;
            int r = idx >> 2, c4 = idx & 3;
            int grow = rowBase + r;
            float4 v = (grow < N_) ? *(const float4*)(A + (size_t)grow * FD + k0 + c4 * 4)
                                   : make_float4(0, 0, 0, 0);
            As[c4 * 4 + 0][r] = v.x;
            As[c4 * 4 + 1][r] = v.y;
            As[c4 * 4 + 2][r] = v.z;
            As[c4 * 4 + 3][r] = v.w;
        }
#pragma unroll
        for (int ld = 0; ld < 2; ld++) {
            int idx = tid + ld * 256;
            int r = idx >> 5, c4 = idx & 31;
            float4 v = *(const float4*)(W + (size_t)(k0 + r) * FD + colBase + c4 * 4);
            *(float4*)(&Bs[r][c4 * 4]) = v;
        }
        __syncthreads();
#pragma unroll
        for (int k = 0; k < BK; k++) {
            float ra[TM], rb[TN];
            *(float4*)(&ra[0]) = *(const float4*)(&As[k][ty * TM]);
            *(float4*)(&ra[4]) = *(const float4*)(&As[k][ty * TM + 4]);
            *(float4*)(&rb[0]) = *(const float4*)(&Bs[k][tx * TN]);
            *(float4*)(&rb[4]) = *(const float4*)(&Bs[k][tx * TN + 4]);
#pragma unroll
            for (int i = 0; i < TM; i++)
#pragma unroll
                for (int j = 0; j < TN; j++) acc[i][j] = fmaf(ra[i], rb[j], acc[i][j]);
        }
        __syncthreads();
    }

    const float* O = g_out[dual];
#pragma unroll
    for (int i = 0; i < TM; i++) {
        int n = rowBase + ty * TM + i;
        if (n >= N_) continue;
#pragma unroll
        for (int j = 0; j < TN; j++) {
            int c = colBase + tx * TN + j;
            float g = 1.f / (1.f + __expf(-(acc[i][j] + bias[c])));
            float o = O[(size_t)n * FD + c];
            float pf = A[(size_t)n * FD + c];
            out[(size_t)n * (2 * FD) + dual * FD + c] = g * o + (1.f - g) * pf;
        }
    }
}

// ------------------------ launch ------------------------------------------------
extern "C" void kernel_launch(void* const* d_in, const int* in_sizes, int n_in,
                              void* d_out, int out_size) {
    const float* ent_emb = (const float*)d_in[0];
    const float* rel_emb = (const float*)d_in[1];
    const int* edge_src  = (const int*)d_in[2];
    const int* edge_dst  = (const int*)d_in[3];
    const int* edge_rel  = (const int*)d_in[4];
    const float* attn_e  = (const float*)d_in[5];
    const float* gate_e  = (const float*)d_in[6];
    const float* proxy_e = (const float*)d_in[7];
    const float* bias_e  = (const float*)d_in[8];
    const float* attn_r  = (const float*)d_in[9];
    const float* gate_r  = (const float*)d_in[10];
    const float* proxy_r = (const float*)d_in[11];
    const float* bias_r  = (const float*)d_in[12];

    int N_ = in_sizes[0] / FF;
    int R_ = in_sizes[1] / FF;
    int E_ = in_sizes[2];
    float* out = (float*)d_out;

    zero_deg_kernel<<<(N_ + 255) / 256, 256>>>(N_);
    count_kernel<<<(E_ + 255) / 256, 256>>>(edge_dst, E_);
    scan_kernel<<<1, 1024>>>(N_);
    scatter_kernel<<<(E_ + 255) / 256, 256>>>(edge_dst, E_);
    relnorm_kernel<<<(R_ * 32 + 255) / 256, 256>>>(rel_emb, attn_e, attn_r, R_);
    stats_kernel<<<1184, 256>>>(edge_rel, N_, R_);
    init_kernel<<<(N_ * 32 + 255) / 256, 256>>>(ent_emb, rel_emb, edge_src, edge_rel, N_);

    for (int l = 0; l < 2; l++)
        layer_kernel<<<(N_ * 32 + 255) / 256, 256>>>(edge_src, edge_rel, 0, l, N_, R_);
    for (int l = 0; l < 2; l++)
        layer_kernel<<<(N_ * 32 + 255) / 256, 256>>>(edge_src, edge_rel, 1, l, N_, R_);

    pinv_kernel<<<16, 256>>>(proxy_e, proxy_r);

    size_t f1sh = (size_t)(PP * 385 + 8 * FD + 8 * PP + PP) * sizeof(float);
    cudaFuncSetAttribute(f1_kernel, cudaFuncAttributeMaxDynamicSharedMemorySize, (int)f1sh);
    f1_kernel<<<1184, 256, f1sh>>>(proxy_e, 0, N_);
    f1_kernel<<<1184, 256, f1sh>>>(proxy_r, 1, N_);

    dim3 g2(FD / BN, (N_ + BM - 1) / BM);
    f2_kernel<<<g2, 256>>>(gate_e, bias_e, 0, out, N_);
    f2_kernel<<<g2, 256>>>(gate_r, bias_r, 1, out, N_);
}

// round 3
// speedup vs baseline: 1.1647x; 1.1647x over previous
#include <cuda_runtime.h>
#include <math.h>

#define MAXN 50000
#define MAXE 800000
#define MAXR 2000
#define FF   128
#define FD   384
#define PP   64
#define EPSV 1e-12f

// ------------------------ scratch (device globals, no allocs) ------------------
__device__ int   g_deg[MAXN];
__device__ int   g_rowptr[MAXN + 1];
__device__ int   g_cursor[MAXN];
__device__ int   g_perm[MAXE];
__device__ float g_relnorm[MAXR * FF];
__device__ float g_ttab[4 * MAXR];
__device__ float g_smax[4 * MAXN];
__device__ float g_ssum[4 * MAXN];
__device__ float g_out[2][(size_t)MAXN * FD];
__device__ float g_pf[2][(size_t)MAXN * FD];
__device__ float g_pn[2][PP * FD];              // normalized*pinv proxy rows
__device__ float g_s[2][(size_t)MAXN * PP];     // raw proxy logits
__device__ float g_att[2][(size_t)MAXN * PP];   // softmaxed attention
__device__ float g_oninv[2][MAXN];              // 1/||O_row||

__device__ __forceinline__ float wsum(float v) {
#pragma unroll
    for (int o = 16; o; o >>= 1) v += __shfl_xor_sync(0xffffffffu, v, o);
    return v;
}
__device__ __forceinline__ float wmax(float v) {
#pragma unroll
    for (int o = 16; o; o >>= 1) v = fmaxf(v, __shfl_xor_sync(0xffffffffu, v, o));
    return v;
}

// ------------------------ packed f32x2 helpers ---------------------------------
__device__ __forceinline__ unsigned long long pack2(float x) {
    unsigned long long r;
    unsigned u = __float_as_uint(x);
    asm("mov.b64 %0, {%1, %1};" : "=l"(r) : "r"(u));
    return r;
}
__device__ __forceinline__ void fma2(unsigned long long& d, unsigned long long a,
                                     unsigned long long b) {
    asm("fma.rn.f32x2 %0, %1, %2, %0;" : "+l"(d) : "l"(a), "l"(b));
}
__device__ __forceinline__ float lo32(unsigned long long v) {
    return __uint_as_float((unsigned)v);
}
__device__ __forceinline__ float hi32(unsigned long long v) {
    return __uint_as_float((unsigned)(v >> 32));
}

// ------------------------ CSR build ------------------------
__global__ void zero_deg_kernel(int N_) {
    int i = blockIdx.x * blockDim.x + threadIdx.x;
    if (i < N_) g_deg[i] = 0;
}

__global__ void count_kernel(const int* __restrict__ edst, int E_) {
    int e = blockIdx.x * blockDim.x + threadIdx.x;
    if (e < E_) atomicAdd(&g_deg[edst[e]], 1);
}

__global__ void scan_kernel(int N_) {
    __shared__ int sh[1024];
    __shared__ int carry;
    if (threadIdx.x == 0) carry = 0;
    __syncthreads();
    for (int base = 0; base < N_; base += 1024) {
        int i = base + threadIdx.x;
        int v = (i < N_) ? g_deg[i] : 0;
        sh[threadIdx.x] = v;
        __syncthreads();
#pragma unroll
        for (int off = 1; off < 1024; off <<= 1) {
            int t = (threadIdx.x >= off) ? sh[threadIdx.x - off] : 0;
            __syncthreads();
            sh[threadIdx.x] += t;
            __syncthreads();
        }
        int inc = sh[threadIdx.x];
        int exc = inc - v + carry;
        if (i < N_) { g_rowptr[i] = exc; g_cursor[i] = exc; }
        __syncthreads();
        if (threadIdx.x == 1023) carry += sh[1023];
        __syncthreads();
    }
    if (threadIdx.x == 0) g_rowptr[N_] = carry;
}

__global__ void scatter_kernel(const int* __restrict__ edst, int E_) {
    int e = blockIdx.x * blockDim.x + threadIdx.x;
    if (e < E_) {
        int p = atomicAdd(&g_cursor[edst[e]], 1);
        g_perm[p] = e;
    }
}

// ------------------------ relation normalization + attn tables ------------------
__global__ void relnorm_kernel(const float* __restrict__ rel,
                               const float* __restrict__ attn_e,
                               const float* __restrict__ attn_r, int R_) {
    int w = (blockIdx.x * blockDim.x + threadIdx.x) >> 5;
    int lane = threadIdx.x & 31;
    if (w >= R_) return;
    float4 v = *(const float4*)(rel + (size_t)w * FF + lane * 4);
    float ss = v.x * v.x + v.y * v.y + v.z * v.z + v.w * v.w;
    ss = wsum(ss);
    float inv = 1.f / fmaxf(sqrtf(ss), EPSV);
    float4 rn = make_float4(v.x * inv, v.y * inv, v.z * inv, v.w * inv);
    *(float4*)(g_relnorm + (size_t)w * FF + lane * 4) = rn;

    float4 a0 = *(const float4*)(attn_e + lane * 4);
    float4 a1 = *(const float4*)(attn_e + FF + lane * 4);
    float4 a2 = *(const float4*)(attn_r + lane * 4);
    float4 a3 = *(const float4*)(attn_r + FF + lane * 4);
    float d0 = wsum(rn.x * a0.x + rn.y * a0.y + rn.z * a0.z + rn.w * a0.w);
    float d1 = wsum(rn.x * a1.x + rn.y * a1.y + rn.z * a1.z + rn.w * a1.w);
    float d2 = wsum(rn.x * a2.x + rn.y * a2.y + rn.z * a2.z + rn.w * a2.w);
    float d3 = wsum(rn.x * a3.x + rn.y * a3.y + rn.z * a3.z + rn.w * a3.w);
    if (lane == 0) {
        g_ttab[0 * R_ + w] = d0;
        g_ttab[1 * R_ + w] = d1;
        g_ttab[2 * R_ + w] = d2;
        g_ttab[3 * R_ + w] = d3;
    }
}

// ------------------------ edge-softmax stats (all 4 tables at once) -------------
__global__ void __launch_bounds__(256) stats_kernel(const int* __restrict__ erel, int N_, int R_) {
    __shared__ float tab[4 * MAXR];
    int tid = threadIdx.x;
    for (int i = tid; i < 4 * R_; i += blockDim.x) tab[i] = g_ttab[i];
    __syncthreads();
    int warp = tid >> 5, lane = tid & 31;
    for (int n = blockIdx.x * 8 + warp; n < N_; n += gridDim.x * 8) {
        int s = g_rowptr[n], e = g_rowptr[n + 1];
        float m0 = -1e30f, m1 = -1e30f, m2 = -1e30f, m3 = -1e30f;
        for (int i = s + lane; i < e; i += 32) {
            int r = erel[g_perm[i]];
            m0 = fmaxf(m0, tab[r]);
            m1 = fmaxf(m1, tab[R_ + r]);
            m2 = fmaxf(m2, tab[2 * R_ + r]);
            m3 = fmaxf(m3, tab[3 * R_ + r]);
        }
        m0 = wmax(m0); m1 = wmax(m1); m2 = wmax(m2); m3 = wmax(m3);
        float s0 = 0, s1 = 0, s2 = 0, s3 = 0;
        for (int i = s + lane; i < e; i += 32) {
            int r = erel[g_perm[i]];
            s0 += __expf(tab[r] - m0);
            s1 += __expf(tab[R_ + r] - m1);
            s2 += __expf(tab[2 * R_ + r] - m2);
            s3 += __expf(tab[3 * R_ + r] - m3);
        }
        s0 = wsum(s0); s1 = wsum(s1); s2 = wsum(s2); s3 = wsum(s3);
        if (lane == 0) {
            g_smax[0 * N_ + n] = m0; g_ssum[0 * N_ + n] = s0;
            g_smax[1 * N_ + n] = m1; g_ssum[1 * N_ + n] = s1;
            g_smax[2 * N_ + n] = m2; g_ssum[2 * N_ + n] = s2;
            g_smax[3 * N_ + n] = m3; g_ssum[3 * N_ + n] = s3;
        }
    }
}

// ------------------------ initial mean features (both duals) --------------------
__global__ void __launch_bounds__(256) init_kernel(const float* __restrict__ ent,
                                                   const float* __restrict__ rel,
                                                   const int* __restrict__ esrc,
                                                   const int* __restrict__ erel, int N_) {
    int w = (blockIdx.x * blockDim.x + threadIdx.x) >> 5;
    if (w >= N_) return;
    int lane = threadIdx.x & 31;
    int s = g_rowptr[w], e = g_rowptr[w + 1];
    float4 ae = make_float4(0, 0, 0, 0), ar = make_float4(0, 0, 0, 0);
    for (int i = s; i < e; i++) {
        int ed = g_perm[i];
        int u = esrc[ed], r = erel[ed];
        float4 fe = *(const float4*)(ent + (size_t)u * FF + lane * 4);
        float4 fr = *(const float4*)(rel + (size_t)r * FF + lane * 4);
        ae.x += fe.x; ae.y += fe.y; ae.z += fe.z; ae.w += fe.w;
        ar.x += fr.x; ar.y += fr.y; ar.z += fr.z; ar.w += fr.w;
    }
    float inv = 1.f / fmaxf((float)(e - s), 1.f);
    float* oe = &g_out[0][(size_t)w * FD + lane * 4];
    float* orr = &g_out[1][(size_t)w * FD + lane * 4];
    oe[0] = tanhf(ae.x * inv); oe[1] = tanhf(ae.y * inv);
    oe[2] = tanhf(ae.z * inv); oe[3] = tanhf(ae.w * inv);
    orr[0] = tanhf(ar.x * inv); orr[1] = tanhf(ar.y * inv);
    orr[2] = tanhf(ar.z * inv); orr[3] = tanhf(ar.w * inv);
}

// ------------------------ GNN layer (both duals per launch) ---------------------
__global__ void __launch_bounds__(256) layer_kernel(const int* __restrict__ esrc,
                                                    const int* __restrict__ erel,
                                                    int layer, int N_, int R_) {
    int gw = (blockIdx.x * blockDim.x + threadIdx.x) >> 5;
    if (gw >= 2 * N_) return;
    int dual = gw >= N_;
    int w = gw - dual * N_;
    int lane = threadIdx.x & 31;
    int s = g_rowptr[w], e = g_rowptr[w + 1];
    int t = dual * 2 + layer;
    const float* feats = g_out[dual];
    const float* tt = g_ttab + (size_t)t * R_;
    float smax = g_smax[(size_t)t * N_ + w];
    float invs = (e > s) ? 1.f / g_ssum[(size_t)t * N_ + w] : 0.f;
    int coff = layer * FF + lane * 4;
    float4 acc = make_float4(0, 0, 0, 0);
    for (int i = s; i < e; i++) {
        int ed = g_perm[i];
        int u = esrc[ed], r = erel[ed];
        float4 f = *(const float4*)(feats + (size_t)u * FD + coff);
        float4 rn = *(const float4*)(g_relnorm + (size_t)r * FF + lane * 4);
        float p = f.x * rn.x + f.y * rn.y + f.z * rn.z + f.w * rn.w;
        float dot = wsum(p);
        float wgt = __expf(tt[r] - smax) * invs;
        float c = 2.f * dot * wgt;
        acc.x += wgt * f.x - c * rn.x;
        acc.y += wgt * f.y - c * rn.y;
        acc.z += wgt * f.z - c * rn.z;
        acc.w += wgt * f.w - c * rn.w;
    }
    float* o = &g_out[dual][(size_t)w * FD + (layer + 1) * FF + lane * 4];
    o[0] = tanhf(acc.x); o[1] = tanhf(acc.y);
    o[2] = tanhf(acc.z); o[3] = tanhf(acc.w);
}

// ------------------------ proxy normalization (store normalized rows) -----------
__global__ void pnorm_kernel(const float* __restrict__ pe, const float* __restrict__ pr) {
    int w = (blockIdx.x * blockDim.x + threadIdx.x) >> 5;
    if (w >= 2 * PP) return;
    int lane = threadIdx.x & 31;
    int dual = (w >= PP) ? 1 : 0;
    int row = w & (PP - 1);
    const float* p = dual ? pr : pe;
    float v[12];
    float ss = 0;
#pragma unroll
    for (int j = 0; j < 12; j++) {
        v[j] = p[(size_t)row * FD + lane + 32 * j];
        ss += v[j] * v[j];
    }
    ss = wsum(ss);
    float inv = 1.f / fmaxf(sqrtf(ss), EPSV);
#pragma unroll
    for (int j = 0; j < 12; j++)
        g_pn[dual][(size_t)row * FD + lane + 32 * j] = v[j] * inv;
}

// ------------------------ O row inverse norms -----------------------------------
__global__ void onorm_kernel(int N_) {
    int gw = (blockIdx.x * blockDim.x + threadIdx.x) >> 5;
    if (gw >= 2 * N_) return;
    int dual = gw >= N_;
    int n = gw - dual * N_;
    int lane = threadIdx.x & 31;
    const float* o = g_out[dual] + (size_t)n * FD;
    float ss = 0;
#pragma unroll
    for (int j = 0; j < 12; j++) {
        float v = o[lane + 32 * j];
        ss += v * v;
    }
    ss = wsum(ss);
    if (lane == 0) g_oninv[dual][n] = 1.f / fmaxf(sqrtf(ss), EPSV);
}

// ------------------------ S = O @ Pn^T  [N,64] GEMM -----------------------------
__global__ void __launch_bounds__(256) s_kernel(int N_) {
    __shared__ float As[32][128];
    __shared__ float Bs[32][68];
    int dual = blockIdx.z;
    const float* A = g_out[dual];
    const float* B = g_pn[dual];
    int tid = threadIdx.x;
    int tx = tid & 15, ty = tid >> 4;
    int rowBase = blockIdx.x * 128;
    unsigned long long acc2[8][2];
#pragma unroll
    for (int i = 0; i < 8; i++) { acc2[i][0] = 0ull; acc2[i][1] = 0ull; }

    for (int k0 = 0; k0 < FD; k0 += 32) {
#pragma unroll
        for (int ld = 0; ld < 4; ld++) {
            int slot = tid + 256 * ld;
            int r = slot >> 3, c4 = slot & 7;
            int grow = rowBase + r;
            float4 v = (grow < N_) ? *(const float4*)(A + (size_t)grow * FD + k0 + c4 * 4)
                                   : make_float4(0, 0, 0, 0);
            As[c4 * 4 + 0][r] = v.x;
            As[c4 * 4 + 1][r] = v.y;
            As[c4 * 4 + 2][r] = v.z;
            As[c4 * 4 + 3][r] = v.w;
        }
#pragma unroll
        for (int ld = 0; ld < 2; ld++) {
            int slot = tid + 256 * ld;   // 0..511 over 64 proxies x 8 float4
            int p = slot >> 3, c4 = slot & 7;
            float4 v = *(const float4*)(B + (size_t)p * FD + k0 + c4 * 4);
            Bs[c4 * 4 + 0][p] = v.x;
            Bs[c4 * 4 + 1][p] = v.y;
            Bs[c4 * 4 + 2][p] = v.z;
            Bs[c4 * 4 + 3][p] = v.w;
        }
        __syncthreads();
#pragma unroll
        for (int k = 0; k < 32; k++) {
            float ra[8];
            *(float4*)(&ra[0]) = *(const float4*)(&As[k][ty * 8]);
            *(float4*)(&ra[4]) = *(const float4*)(&As[k][ty * 8 + 4]);
            ulonglong2 b = *(const ulonglong2*)(&Bs[k][tx * 4]);
#pragma unroll
            for (int i = 0; i < 8; i++) {
                unsigned long long a2 = pack2(ra[i]);
                fma2(acc2[i][0], a2, b.x);
                fma2(acc2[i][1], a2, b.y);
            }
        }
        __syncthreads();
    }
    float* S = g_s[dual];
#pragma unroll
    for (int i = 0; i < 8; i++) {
        int n = rowBase + ty * 8 + i;
        if (n >= N_) continue;
        float* d = S + (size_t)n * PP + tx * 4;
        d[0] = lo32(acc2[i][0]);
        d[1] = hi32(acc2[i][0]);
        d[2] = lo32(acc2[i][1]);
        d[3] = hi32(acc2[i][1]);
    }
}

// ------------------------ softmax over proxies ----------------------------------
__global__ void att_kernel(int N_) {
    int gw = (blockIdx.x * blockDim.x + threadIdx.x) >> 5;
    if (gw >= 2 * N_) return;
    int dual = gw >= N_;
    int n = gw - dual * N_;
    int lane = threadIdx.x & 31;
    float inv = g_oninv[dual][n];
    const float* S = g_s[dual] + (size_t)n * PP;
    float s0 = S[lane] * inv;
    float s1 = S[lane + 32] * inv;
    float m = wmax(fmaxf(s0, s1));
    float e0 = __expf(s0 - m), e1 = __expf(s1 - m);
    float r = 1.f / wsum(e0 + e1);
    float* A = g_att[dual] + (size_t)n * PP;
    A[lane] = e0 * r;
    A[lane + 32] = e1 * r;
}

// ------------------------ PF = O - Att @ P  [N,384] GEMM (K=64) -----------------
__global__ void __launch_bounds__(256) pf_kernel(const float* __restrict__ pe,
                                                 const float* __restrict__ pr, int N_) {
    __shared__ float As[32][128];
    __shared__ float Bs[32][128];
    int dual = blockIdx.z;
    const float* P = dual ? pr : pe;
    const float* A = g_att[dual];
    int tid = threadIdx.x;
    int tx = tid & 15, ty = tid >> 4;
    int rowBase = blockIdx.y * 128;
    int colBase = blockIdx.x * 128;
    unsigned long long acc2[8][4];
#pragma unroll
    for (int i = 0; i < 8; i++)
#pragma unroll
        for (int j = 0; j < 4; j++) acc2[i][j] = 0ull;

    for (int k0 = 0; k0 < PP; k0 += 32) {
#pragma unroll
        for (int ld = 0; ld < 4; ld++) {
            int slot = tid + 256 * ld;
            int r = slot >> 3, c4 = slot & 7;
            int grow = rowBase + r;
            float4 v = (grow < N_) ? *(const float4*)(A + (size_t)grow * PP + k0 + c4 * 4)
                                   : make_float4(0, 0, 0, 0);
            As[c4 * 4 + 0][r] = v.x;
            As[c4 * 4 + 1][r] = v.y;
            As[c4 * 4 + 2][r] = v.z;
            As[c4 * 4 + 3][r] = v.w;
        }
#pragma unroll
        for (int ld = 0; ld < 4; ld++) {
            int slot = tid + 256 * ld;
            int r = slot >> 5, c4 = slot & 31;
            float4 v = *(const float4*)(P + (size_t)(k0 + r) * FD + colBase + c4 * 4);
            *(float4*)(&Bs[r][c4 * 4]) = v;
        }
        __syncthreads();
#pragma unroll
        for (int k = 0; k < 32; k++) {
            float ra[8];
            *(float4*)(&ra[0]) = *(const float4*)(&As[k][ty * 8]);
            *(float4*)(&ra[4]) = *(const float4*)(&As[k][ty * 8 + 4]);
            ulonglong2 b0 = *(const ulonglong2*)(&Bs[k][tx * 8]);
            ulonglong2 b1 = *(const ulonglong2*)(&Bs[k][tx * 8 + 4]);
#pragma unroll
            for (int i = 0; i < 8; i++) {
                unsigned long long a2 = pack2(ra[i]);
                fma2(acc2[i][0], a2, b0.x);
                fma2(acc2[i][1], a2, b0.y);
                fma2(acc2[i][2], a2, b1.x);
                fma2(acc2[i][3], a2, b1.y);
            }
        }
        __syncthreads();
    }
    const float* O = g_out[dual];
    float* PF = g_pf[dual];
#pragma unroll
    for (int i = 0; i < 8; i++) {
        int n = rowBase + ty * 8 + i;
        if (n >= N_) continue;
        int c = colBase + tx * 8;
        const float* orow = O + (size_t)n * FD + c;
        float* d = PF + (size_t)n * FD + c;
        d[0] = orow[0] - lo32(acc2[i][0]);
        d[1] = orow[1] - hi32(acc2[i][0]);
        d[2] = orow[2] - lo32(acc2[i][1]);
        d[3] = orow[3] - hi32(acc2[i][1]);
        d[4] = orow[4] - lo32(acc2[i][2]);
        d[5] = orow[5] - hi32(acc2[i][2]);
        d[6] = orow[6] - lo32(acc2[i][3]);
        d[7] = orow[7] - hi32(acc2[i][3]);
    }
}

// ------------------------ F2: gate GEMM + final blend ---------------------------
__global__ void __launch_bounds__(256) f2_kernel(const float* __restrict__ We,
                                                 const float* __restrict__ Wr,
                                                 const float* __restrict__ be,
                                                 const float* __restrict__ br,
                                                 float* __restrict__ out, int N_) {
    __shared__ float As[16][128];
    __shared__ float Bs[16][128];
    int dual = blockIdx.z;
    const float* W = dual ? Wr : We;
    const float* bias = dual ? br : be;
    int tid = threadIdx.x;
    int tx = tid & 15, ty = tid >> 4;
    int rowBase = blockIdx.y * 128;
    int colBase = blockIdx.x * 128;
    const float* A = g_pf[dual];
    unsigned long long acc2[8][4];
#pragma unroll
    for (int i = 0; i < 8; i++)
#pragma unroll
        for (int j = 0; j < 4; j++) acc2[i][j] = 0ull;

    for (int k0 = 0; k0 < FD; k0 += 16) {
#pragma unroll
        for (int ld = 0; ld < 2; ld++) {
            int idx = tid + ld * 256;
            int r = idx >> 2, c4 = idx & 3;
            int grow = rowBase + r;
            float4 v = (grow < N_) ? *(const float4*)(A + (size_t)grow * FD + k0 + c4 * 4)
                                   : make_float4(0, 0, 0, 0);
            As[c4 * 4 + 0][r] = v.x;
            As[c4 * 4 + 1][r] = v.y;
            As[c4 * 4 + 2][r] = v.z;
            As[c4 * 4 + 3][r] = v.w;
        }
#pragma unroll
        for (int ld = 0; ld < 2; ld++) {
            int idx = tid + ld * 256;
            int r = idx >> 5, c4 = idx & 31;
            float4 v = *(const float4*)(W + (size_t)(k0 + r) * FD + colBase + c4 * 4);
            *(float4*)(&Bs[r][c4 * 4]) = v;
        }
        __syncthreads();
#pragma unroll
        for (int k = 0; k < 16; k++) {
            float ra[8];
            *(float4*)(&ra[0]) = *(const float4*)(&As[k][ty * 8]);
            *(float4*)(&ra[4]) = *(const float4*)(&As[k][ty * 8 + 4]);
            ulonglong2 b0 = *(const ulonglong2*)(&Bs[k][tx * 8]);
            ulonglong2 b1 = *(const ulonglong2*)(&Bs[k][tx * 8 + 4]);
#pragma unroll
            for (int i = 0; i < 8; i++) {
                unsigned long long a2 = pack2(ra[i]);
                fma2(acc2[i][0], a2, b0.x);
                fma2(acc2[i][1], a2, b0.y);
                fma2(acc2[i][2], a2, b1.x);
                fma2(acc2[i][3], a2, b1.y);
            }
        }
        __syncthreads();
    }

    const float* O = g_out[dual];
#pragma unroll
    for (int i = 0; i < 8; i++) {
        int n = rowBase + ty * 8 + i;
        if (n >= N_) continue;
        float accv[8];
        accv[0] = lo32(acc2[i][0]); accv[1] = hi32(acc2[i][0]);
        accv[2] = lo32(acc2[i][1]); accv[3] = hi32(acc2[i][1]);
        accv[4] = lo32(acc2[i][2]); accv[5] = hi32(acc2[i][2]);
        accv[6] = lo32(acc2[i][3]); accv[7] = hi32(acc2[i][3]);
#pragma unroll
        for (int j = 0; j < 8; j++) {
            int c = colBase + tx * 8 + j;
            float g = 1.f / (1.f + __expf(-(accv[j] + bias[c])));
            float o = O[(size_t)n * FD + c];
            float pf = A[(size_t)n * FD + c];
            out[(size_t)n * (2 * FD) + dual * FD + c] = g * o + (1.f - g) * pf;
        }
    }
}

// ------------------------ launch ------------------------------------------------
extern "C" void kernel_launch(void* const* d_in, const int* in_sizes, int n_in,
                              void* d_out, int out_size) {
    const float* ent_emb = (const float*)d_in[0];
    const float* rel_emb = (const float*)d_in[1];
    const int* edge_src  = (const int*)d_in[2];
    const int* edge_dst  = (const int*)d_in[3];
    const int* edge_rel  = (const int*)d_in[4];
    const float* attn_e  = (const float*)d_in[5];
    const float* gate_e  = (const float*)d_in[6];
    const float* proxy_e = (const float*)d_in[7];
    const float* bias_e  = (const float*)d_in[8];
    const float* attn_r  = (const float*)d_in[9];
    const float* gate_r  = (const float*)d_in[10];
    const float* proxy_r = (const float*)d_in[11];
    const float* bias_r  = (const float*)d_in[12];

    int N_ = in_sizes[0] / FF;
    int R_ = in_sizes[1] / FF;
    int E_ = in_sizes[2];
    float* out = (float*)d_out;

    zero_deg_kernel<<<(N_ + 255) / 256, 256>>>(N_);
    count_kernel<<<(E_ + 255) / 256, 256>>>(edge_dst, E_);
    scan_kernel<<<1, 1024>>>(N_);
    scatter_kernel<<<(E_ + 255) / 256, 256>>>(edge_dst, E_);
    relnorm_kernel<<<(R_ * 32 + 255) / 256, 256>>>(rel_emb, attn_e, attn_r, R_);
    stats_kernel<<<1184, 256>>>(edge_rel, N_, R_);
    init_kernel<<<(N_ * 32 + 255) / 256, 256>>>(ent_emb, rel_emb, edge_src, edge_rel, N_);

    int lgrid = (2 * N_ * 32 + 255) / 256;
    layer_kernel<<<lgrid, 256>>>(edge_src, edge_rel, 0, N_, R_);
    layer_kernel<<<lgrid, 256>>>(edge_src, edge_rel, 1, N_, R_);

    pnorm_kernel<<<16, 256>>>(proxy_e, proxy_r);
    onorm_kernel<<<(2 * N_ * 32 + 255) / 256, 256>>>(N_);

    dim3 gs((N_ + 127) / 128, 1, 2);
    s_kernel<<<gs, 256>>>(N_);
    att_kernel<<<(2 * N_ * 32 + 255) / 256, 256>>>(N_);

    dim3 gpf(FD / 128, (N_ + 127) / 128, 2);
    pf_kernel<<<gpf, 256>>>(proxy_e, proxy_r, N_);

    dim3 g2(FD / 128, (N_ + 127) / 128, 2);
    f2_kernel<<<g2, 256>>>(gate_e, gate_r, bias_e, bias_r, out, N_);
}